// round 16
// baseline (speedup 1.0000x reference)
#include <cuda_runtime.h>
#include <cuda_bf16.h>
#include <math.h>
#include <stdint.h>

#if defined(__CUDA_ARCH_FEAT_SM103_ALL) || defined(__CUDA_ARCH_FEAT_SM100_ALL) || \
    (defined(__CUDA_ARCH_SPECIFIC__) && (__CUDA_ARCH_SPECIFIC__ >= 1000))
#define HAS_TC 1
#else
#define HAS_TC 0
#endif

#define DEPTH   4
#define HEADS   16
#define DIMV    1024
#define DHEAD   64
#define MLPV    4096
#define BV      4
#define NV      1024
#define MV      1024
#define ROWS    (BV * NV)
#define EPSV    1e-5f
#define KVSTR   2048

typedef __nv_bfloat16 bf16;
typedef __nv_bfloat162 bf162;

// ---------------------------------------------------------------------------
// Scratch
// ---------------------------------------------------------------------------
__device__ float g_q  [ROWS * DIMV];   // bf16 q_hi | q_lo
__device__ float g_k  [ROWS * DIMV];   // bf16 kv_hi (ROWS x 2048)
__device__ float g_v  [ROWS * DIMV];   // bf16 kv_lo (ROWS x 2048)
__device__ bf16  g_att_hi[ROWS * DIMV];
__device__ bf16  g_att_lo[ROWS * DIMV];
__device__ bf16  g_h_hi  [ROWS * DIMV];
__device__ bf16  g_h_lo  [ROWS * DIMV];
__device__ bf16  g_wt_hi [MLPV * DIMV];
__device__ bf16  g_wt_lo [MLPV * DIMV];
__device__ bf16  g_ff_hi [ROWS * MLPV];   // front 4M: vt_hi [1024 d][4096 tok]
__device__ bf16  g_ff_lo [ROWS * MLPV];   // front 4M: vt_lo
__device__ bf16  g_m_hi  [ROWS * DIMV];
__device__ bf16  g_m_lo  [ROWS * DIMV];

// ---------------------------------------------------------------------------
// PTX helpers
// ---------------------------------------------------------------------------
__device__ __forceinline__ uint32_t smem_u32(const void* p) {
    uint32_t a;
    asm("{ .reg .u64 t; cvta.to.shared.u64 t, %1; cvt.u32.u64 %0, t; }"
        : "=r"(a) : "l"(p));
    return a;
}

__device__ __forceinline__ uint32_t elect_one_pred() {
    uint32_t pred;
    asm volatile("{\n\t.reg .pred p;\n\t"
                 "elect.sync _|p, 0xFFFFFFFF;\n\t"
                 "selp.b32 %0, 1, 0, p;\n\t}"
                 : "=r"(pred));
    return pred;
}

__device__ __forceinline__ void cpasync16(uint32_t saddr, const void* g) {
    asm volatile("cp.async.cg.shared.global [%0], [%1], 16;\n"
                 :: "r"(saddr), "l"(g));
}
__device__ __forceinline__ void cp_commit() {
    asm volatile("cp.async.commit_group;\n" ::: "memory");
}
template <int N>
__device__ __forceinline__ void cp_wait() {
    asm volatile("cp.async.wait_group %0;\n" :: "n"(N) : "memory");
}

__device__ __forceinline__ void mbar_init(uint32_t addr, uint32_t cnt) {
    asm volatile("mbarrier.init.shared.b64 [%0], %1;" :: "r"(addr), "r"(cnt) : "memory");
}
__device__ __forceinline__ void mbar_wait(uint32_t addr, uint32_t parity) {
    uint32_t done;
    asm volatile("{\n\t.reg .pred p;\n\t"
                 "mbarrier.try_wait.parity.acquire.cta.shared::cta.b64 p, [%1], %2;\n\t"
                 "selp.b32 %0, 1, 0, p;\n\t}\n"
                 : "=r"(done) : "r"(addr), "r"(parity) : "memory");
    while (!done) {
        asm volatile("{\n\t.reg .pred p;\n\t"
                     "mbarrier.try_wait.parity.acquire.cta.shared::cta.b64 p, [%1], %2, 0x989680;\n\t"
                     "selp.b32 %0, 1, 0, p;\n\t}\n"
                     : "=r"(done) : "r"(addr), "r"(parity) : "memory");
    }
}

#if HAS_TC
__device__ __forceinline__ uint64_t make_desc(uint32_t addr) {
    const uint64_t base =
        (uint64_t(2)  << 61) | (uint64_t(1) << 46) |
        (uint64_t(64) << 32) | (uint64_t(1) << 16);
    return base | ((uint64_t)(addr >> 4) & 0x3FFF);
}

__device__ __forceinline__ void mma_f16_ss(uint32_t d_tmem, uint64_t a_desc,
                                           uint64_t b_desc, uint32_t idesc,
                                           uint32_t enable) {
    asm volatile("{\n\t.reg .pred p;\n\t"
                 "setp.ne.u32 p, %4, 0;\n\t"
                 "tcgen05.mma.cta_group::1.kind::f16 [%0], %1, %2, %3, "
                 "{%5, %5, %5, %5}, p;\n\t}"
                 :: "r"(d_tmem), "l"(a_desc), "l"(b_desc), "r"(idesc),
                    "r"(enable), "r"(0u)
                 : "memory");
}

#define TC_ALLOC(smem_addr, n) \
    asm volatile("tcgen05.alloc.cta_group::1.sync.aligned.shared::cta.b32 [%0], %1;" \
                 :: "r"(smem_addr), "r"((uint32_t)(n)) : "memory")
#define TC_DEALLOC(tmem, n) \
    asm volatile("tcgen05.dealloc.cta_group::1.sync.aligned.b32 %0, %1;" \
                 :: "r"(tmem), "r"((uint32_t)(n)))
#define TC_COMMIT(mbar) \
    asm volatile("tcgen05.commit.cta_group::1.mbarrier::arrive::one.shared::cluster.b64 [%0];" \
                 :: "r"(mbar) : "memory")
#define TC_FENCE_AFTER() \
    asm volatile("tcgen05.fence::after_thread_sync;" ::: "memory")
#define TC_WAIT_LD() \
    asm volatile("tcgen05.wait::ld.sync.aligned;" ::: "memory")

#define TC_LD_X32(r, addr) \
    asm volatile( \
        "tcgen05.ld.sync.aligned.32x32b.x32.b32 " \
        "{%0, %1, %2, %3, %4, %5, %6, %7, " \
        " %8, %9, %10, %11, %12, %13, %14, %15, " \
        " %16, %17, %18, %19, %20, %21, %22, %23, " \
        " %24, %25, %26, %27, %28, %29, %30, %31}, [%32];" \
        : "=r"((r)[0]),  "=r"((r)[1]),  "=r"((r)[2]),  "=r"((r)[3]), \
          "=r"((r)[4]),  "=r"((r)[5]),  "=r"((r)[6]),  "=r"((r)[7]), \
          "=r"((r)[8]),  "=r"((r)[9]),  "=r"((r)[10]), "=r"((r)[11]), \
          "=r"((r)[12]), "=r"((r)[13]), "=r"((r)[14]), "=r"((r)[15]), \
          "=r"((r)[16]), "=r"((r)[17]), "=r"((r)[18]), "=r"((r)[19]), \
          "=r"((r)[20]), "=r"((r)[21]), "=r"((r)[22]), "=r"((r)[23]), \
          "=r"((r)[24]), "=r"((r)[25]), "=r"((r)[26]), "=r"((r)[27]), \
          "=r"((r)[28]), "=r"((r)[29]), "=r"((r)[30]), "=r"((r)[31]) \
        : "r"(addr))
#endif  // HAS_TC

// ---------------------------------------------------------------------------
// splits
// ---------------------------------------------------------------------------
__device__ __forceinline__ void bf16_split(float v, bf16& hi, bf16& lo) {
    hi = __float2bfloat16_rn(v);
    lo = __float2bfloat16_rn(v - __bfloat162float(hi));
}

__device__ __forceinline__ void bf16_split4(const float* v, bf162* h2, bf162* l2) {
    bf16 h[4], l[4];
    #pragma unroll
    for (int i = 0; i < 4; i++) bf16_split(v[i], h[i], l[i]);
    h2[0] = bf162(h[0], h[1]); h2[1] = bf162(h[2], h[3]);
    l2[0] = bf162(l[0], l[1]); l2[1] = bf162(l[2], l[3]);
}

__global__ void split_kernel(const float4* __restrict__ x,
                             bf162* __restrict__ hi, bf162* __restrict__ lo,
                             int n4) {
    int i = blockIdx.x * 256 + threadIdx.x;
    if (i >= n4) return;
    float4 v = x[i];
    float vv[4] = {v.x, v.y, v.z, v.w};
    bf162 h2[2], l2[2];
    bf16_split4(vv, h2, l2);
    hi[i * 2] = h2[0]; hi[i * 2 + 1] = h2[1];
    lo[i * 2] = l2[0]; lo[i * 2 + 1] = l2[1];
}

// transpose + split: W[K,N] fp32 -> Thi/Tlo [N,K] bf16
__global__ void tsplit_kernel(const float* __restrict__ W,
                              bf16* __restrict__ Thi, bf16* __restrict__ Tlo,
                              int K, int N) {
    __shared__ float tile[32][33];
    int n0 = blockIdx.x * 32, k0 = blockIdx.y * 32;
    int tx = threadIdx.x, ty = threadIdx.y;   // 32 x 8
    #pragma unroll
    for (int i = 0; i < 32; i += 8)
        tile[ty + i][tx] = W[(size_t)(k0 + ty + i) * N + n0 + tx];
    __syncthreads();
    #pragma unroll
    for (int i = 0; i < 32; i += 8) {
        float v = tile[tx][ty + i];
        bf16 h, l;
        bf16_split(v, h, l);
        size_t o = (size_t)(n0 + ty + i) * K + k0 + tx;
        Thi[o] = h; Tlo[o] = l;
    }
}

// ---------------------------------------------------------------------------
// GEMM (3xBF16): C[M,N] = A @ W. Tile 128x128, single 64KB stage,
// serial load->MMA per chunk; occupancy 3 CTAs/SM provides the overlap.
// DO_VT: for cols >= DIMV store transposed vt[d][token] (KV projection).
// ---------------------------------------------------------------------------
#define GEMM_SMEM (65536 + 2048)
#define IDESC_BF16 ((1u << 4) | (1u << 7) | (1u << 10) | ((128u / 8) << 17) | ((128u / 16) << 24))

__device__ __forceinline__ void load_tile128x64(uint32_t sbase,
                                                const bf16* __restrict__ g,
                                                int ld) {
    int t = threadIdx.x;
    #pragma unroll
    for (int i = 0; i < 4; i++) {
        int e = i * 256 + t;
        int row = e >> 3, c16 = e & 7;
        uint32_t boff = row * 128 + c16 * 16;
        uint32_t sw = boff ^ ((boff >> 3) & 0x70);
        cpasync16(sbase + sw, g + (size_t)row * ld + c16 * 8);
    }
}

template <int DO_GELU, int DO_RES, int DO_SPLIT, int DO_VT>
__global__ void __launch_bounds__(256)
gemm_bf16(const bf16* __restrict__ Ahi, const bf16* __restrict__ Alo,
          const bf16* __restrict__ Bhi, const bf16* __restrict__ Blo,
          const float* __restrict__ bias, const float* __restrict__ R,
          float* __restrict__ C, bf16* __restrict__ Chi, bf16* __restrict__ Clo,
          bf16* __restrict__ Vthi, bf16* __restrict__ Vtlo,
          int K, int Nc) {
#if HAS_TC
    extern __shared__ char smem[];
    uint32_t sb = smem_u32(smem);
    uint32_t db = (sb + 32 + 1023u) & ~1023u;
    int tid = threadIdx.x;
    int wid = tid >> 5;

    if (wid == 0) { TC_ALLOC(sb + 0, 128); }
    if (tid == 0) { mbar_init(sb + 8, 1); }
    __syncthreads();
    uint32_t tmem;
    asm volatile("ld.shared.b32 %0, [%1];" : "=r"(tmem) : "r"(sb + 0));

    int m0 = blockIdx.y * 128;
    int n0 = blockIdx.x * 128;
    const bf16* aH = Ahi + (size_t)m0 * K;
    const bf16* aL = Alo + (size_t)m0 * K;
    const bf16* bH = Bhi + (size_t)n0 * K;
    const bf16* bL = Blo + (size_t)n0 * K;

    const int CH = K / 64;
    uint32_t ph = 0;

    for (int c = 0; c < CH; c++) {
        if (c > 0) { mbar_wait(sb + 8, ph); ph ^= 1; }   // MMA(c-1) done
        int kc = c * 64;
        load_tile128x64(db,         aH + kc, K);
        load_tile128x64(db + 16384, aL + kc, K);
        load_tile128x64(db + 32768, bH + kc, K);
        load_tile128x64(db + 49152, bL + kc, K);
        cp_commit();
        cp_wait<0>();
        asm volatile("fence.proxy.async.shared::cta;" ::: "memory");
        __syncthreads();
        if (wid == 0) {
            if (elect_one_pred()) {
                uint64_t dAh = make_desc(db);
                uint64_t dAl = make_desc(db + 16384);
                uint64_t dBh = make_desc(db + 32768);
                uint64_t dBl = make_desc(db + 49152);
                #pragma unroll
                for (int k = 0; k < 4; k++) {
                    uint32_t en = (c > 0) || (k > 0);
                    mma_f16_ss(tmem, dAh + 2 * k, dBh + 2 * k, IDESC_BF16, en);
                    mma_f16_ss(tmem, dAh + 2 * k, dBl + 2 * k, IDESC_BF16, 1u);
                    mma_f16_ss(tmem, dAl + 2 * k, dBh + 2 * k, IDESC_BF16, 1u);
                }
                TC_COMMIT(sb + 8);
            }
        }
    }
    mbar_wait(sb + 8, ph);
    TC_FENCE_AFTER();

    if (wid < 4) {
        int lane = tid & 31;
        int row = m0 + wid * 32 + lane;
        #pragma unroll
        for (int b4 = 0; b4 < 4; b4++) {
            uint32_t r[32];
            TC_LD_X32(r, tmem + b4 * 32);
            TC_WAIT_LD();
            float vals[32];
            #pragma unroll
            for (int j = 0; j < 32; j++) {
                float v = __uint_as_float(r[j]);
                int col = n0 + b4 * 32 + j;
                if (bias) v += bias[col];
                if (DO_GELU) v = 0.5f * v * (1.0f + erff(v * 0.70710678118654752f));
                if (DO_RES) v += R[(size_t)row * Nc + col];
                vals[j] = v;
            }
            if (DO_VT && (n0 + b4 * 32) >= DIMV) {
                #pragma unroll
                for (int j = 0; j < 32; j++) {
                    int d = n0 + b4 * 32 + j - DIMV;
                    bf16 hh, ll;
                    bf16_split(vals[j], hh, ll);
                    Vthi[(size_t)d * ROWS + row] = hh;
                    Vtlo[(size_t)d * ROWS + row] = ll;
                }
            } else if (DO_SPLIT) {
                #pragma unroll
                for (int j4 = 0; j4 < 8; j4++) {
                    bf162 h2[2], l2[2];
                    bf16_split4(&vals[j4 * 4], h2, l2);
                    size_t o = (size_t)row * Nc + n0 + b4 * 32 + j4 * 4;
                    *(uint2*)&Chi[o] = *(uint2*)h2;
                    *(uint2*)&Clo[o] = *(uint2*)l2;
                }
            } else {
                #pragma unroll
                for (int j4 = 0; j4 < 8; j4++) {
                    *(float4*)&C[(size_t)row * Nc + n0 + b4 * 32 + j4 * 4] =
                        make_float4(vals[j4*4], vals[j4*4+1],
                                    vals[j4*4+2], vals[j4*4+3]);
                }
            }
        }
    }
    __syncthreads();
    if (wid == 0) { TC_DEALLOC(tmem, 128); }
#else
    // ---- scalar fallback (plain sm_103 pass only) ----
    extern __shared__ char smem[];
    float* As = (float*)smem;
    float* Bs = As + 16 * 128;
    int tid = threadIdx.x;
    int tx = tid & 15, ty = tid >> 4;
    int m0 = blockIdx.y * 128;
    int n0 = blockIdx.x * 128;

    float acc[8][8];
    #pragma unroll
    for (int i = 0; i < 8; i++)
        #pragma unroll
        for (int j = 0; j < 8; j++) acc[i][j] = 0.f;

    for (int k0 = 0; k0 < K; k0 += 16) {
        __syncthreads();
        #pragma unroll
        for (int e = 0; e < 8; e++) {
            int idx = e * 256 + tid;
            int rr = idx >> 4, kk = idx & 15;
            As[kk * 128 + rr] =
                __bfloat162float(Ahi[(size_t)(m0 + rr) * K + k0 + kk]) +
                __bfloat162float(Alo[(size_t)(m0 + rr) * K + k0 + kk]);
            Bs[kk * 128 + rr] =
                __bfloat162float(Bhi[(size_t)(n0 + rr) * K + k0 + kk]) +
                __bfloat162float(Blo[(size_t)(n0 + rr) * K + k0 + kk]);
        }
        __syncthreads();
        #pragma unroll
        for (int k = 0; k < 16; k++) {
            float ar[8], br[8];
            #pragma unroll
            for (int i = 0; i < 8; i++) ar[i] = As[k * 128 + ty * 8 + i];
            #pragma unroll
            for (int j = 0; j < 8; j++) br[j] = Bs[k * 128 + tx * 8 + j];
            #pragma unroll
            for (int i = 0; i < 8; i++)
                #pragma unroll
                for (int j = 0; j < 8; j++)
                    acc[i][j] += ar[i] * br[j];
        }
    }
    #pragma unroll
    for (int i = 0; i < 8; i++) {
        int row = m0 + ty * 8 + i;
        #pragma unroll
        for (int j = 0; j < 8; j++) {
            int col = n0 + tx * 8 + j;
            float v = acc[i][j];
            if (bias) v += bias[col];
            if (DO_GELU) v = 0.5f * v * (1.0f + erff(v * 0.70710678118654752f));
            size_t idx = (size_t)row * Nc + col;
            if (DO_VT && col >= DIMV) {
                bf16 hh, ll;
                bf16_split(v, hh, ll);
                Vthi[(size_t)(col - DIMV) * ROWS + row] = hh;
                Vtlo[(size_t)(col - DIMV) * ROWS + row] = ll;
            } else if (DO_SPLIT) {
                bf16 hh, ll;
                bf16_split(v, hh, ll);
                Chi[idx] = hh; Clo[idx] = ll;
            } else {
                if (DO_RES) v += R[idx];
                C[idx] = v;
            }
        }
    }
#endif
}

// ---------------------------------------------------------------------------
// LayerNorm with fused bf16 split output
// ---------------------------------------------------------------------------
__global__ void ln_split_kernel(const float* __restrict__ x,
                                const float* __restrict__ w,
                                const float* __restrict__ b,
                                bf16* __restrict__ yhi,
                                bf16* __restrict__ ylo) {
    int row = blockIdx.x;
    int t   = threadIdx.x;
    const float4* xr = (const float4*)(x + (size_t)row * DIMV);
    float4 xv = xr[t];

    float s = xv.x + xv.y + xv.z + xv.w;
    float q = xv.x * xv.x + xv.y * xv.y + xv.z * xv.z + xv.w * xv.w;
    #pragma unroll
    for (int off = 16; off; off >>= 1) {
        s += __shfl_xor_sync(0xffffffffu, s, off);
        q += __shfl_xor_sync(0xffffffffu, q, off);
    }
    __shared__ float ss[8], sq[8];
    int wid = t >> 5, lane = t & 31;
    if (lane == 0) { ss[wid] = s; sq[wid] = q; }
    __syncthreads();
    if (t == 0) {
        float S = 0.f, Q = 0.f;
        #pragma unroll
        for (int i = 0; i < 8; i++) { S += ss[i]; Q += sq[i]; }
        ss[0] = S; sq[0] = Q;
    }
    __syncthreads();
    float mu   = ss[0] * (1.0f / DIMV);
    float var  = sq[0] * (1.0f / DIMV) - mu * mu;
    float rstd = rsqrtf(var + EPSV);

    float4 wv = ((const float4*)w)[t];
    float4 bv = ((const float4*)b)[t];
    float o[4];
    o[0] = (xv.x - mu) * rstd * wv.x + bv.x;
    o[1] = (xv.y - mu) * rstd * wv.y + bv.y;
    o[2] = (xv.z - mu) * rstd * wv.z + bv.z;
    o[3] = (xv.w - mu) * rstd * wv.w + bv.w;
    bf162 h2[2], l2[2];
    bf16_split4(o, h2, l2);
    size_t oo = (size_t)row * DIMV + t * 4;
    *(uint2*)&yhi[oo] = *(uint2*)h2;
    *(uint2*)&ylo[oo] = *(uint2*)l2;
}

// ---------------------------------------------------------------------------
// Tensor-core flash attention (unchanged from round 15)
// ---------------------------------------------------------------------------
#define AQ_HI  0
#define AQ_LO  16384
#define AKS0   32768
#define AVS0   98304
#define AP     163840
#define AL_OFF 196608
#define ATTN_SMEM (197632 + 2048)

#define IDESC_S ((1u << 4) | (1u << 7) | (1u << 10) | ((128u / 8) << 17) | ((128u / 16) << 24))
#define IDESC_O ((1u << 4) | (1u << 7) | (1u << 10) | ((64u  / 8) << 17) | ((128u / 16) << 24))

__global__ void __launch_bounds__(256)
attn_tc(const bf16* __restrict__ qhi, const bf16* __restrict__ qlo,
        const bf16* __restrict__ kvhi, const bf16* __restrict__ kvlo,
        const bf16* __restrict__ vthi, const bf16* __restrict__ vtlo,
        bf16* __restrict__ ohi, bf16* __restrict__ olo) {
#if HAS_TC
    extern __shared__ char smem[];
    uint32_t sb = smem_u32(smem);
    uint32_t db = (sb + 32 + 1023u) & ~1023u;
    char* dbp = smem + (db - sb);
    int tid = threadIdx.x;
    int wid = tid >> 5;
    int lane = tid & 31;
    int qt = blockIdx.x, h = blockIdx.y, b = blockIdx.z;

    if (wid == 0) { TC_ALLOC(sb + 0, 256); }
    if (tid == 0) { mbar_init(sb + 8, 1); mbar_init(sb + 16, 1); }
    __syncthreads();
    uint32_t tmem;
    asm volatile("ld.shared.b32 %0, [%1];" : "=r"(tmem) : "r"(sb + 0));

    auto load_tile = [&](int jt2, int s) {
        uint32_t ks = db + AKS0 + (uint32_t)s * 32768u;
        uint32_t vs = db + AVS0 + (uint32_t)s * 32768u;
        const size_t kb = ((size_t)(b * MV) + jt2 * 128) * KVSTR + h * DHEAD;
        #pragma unroll
        for (int i = 0; i < 4; i++) {
            int e = i * 256 + tid;
            int row = e >> 3, c16 = e & 7;
            uint32_t boff = row * 128 + c16 * 16;
            uint32_t sw = boff ^ ((boff >> 3) & 0x70);
            cpasync16(ks + sw,         kvhi + kb + (size_t)row * KVSTR + c16 * 8);
            cpasync16(ks + 16384 + sw, kvlo + kb + (size_t)row * KVSTR + c16 * 8);
        }
        const size_t vtb = (size_t)(h * DHEAD) * ROWS + (size_t)b * NV + jt2 * 128;
        #pragma unroll
        for (int i = 0; i < 4; i++) {
            int e = i * 256 + tid;
            int d = e >> 4, ch = (e >> 3) & 1, k8 = e & 7;
            uint32_t boff = d * 128 + k8 * 16;
            uint32_t sw = boff ^ ((boff >> 3) & 0x70);
            size_t src = vtb + (size_t)d * ROWS + ch * 64 + k8 * 8;
            cpasync16(vs + ch * 8192 + sw,         vthi + src);
            cpasync16(vs + 16384 + ch * 8192 + sw, vtlo + src);
        }
    };

    const size_t qb = ((size_t)(b * NV) + qt * 128) * DIMV + h * DHEAD;
    #pragma unroll
    for (int i = 0; i < 4; i++) {
        int e = i * 256 + tid;
        int row = e >> 3, c16 = e & 7;
        uint32_t boff = row * 128 + c16 * 16;
        uint32_t sw = boff ^ ((boff >> 3) & 0x70);
        cpasync16(db + AQ_HI + sw, qhi + qb + (size_t)row * DIMV + c16 * 8);
        cpasync16(db + AQ_LO + sw, qlo + qb + (size_t)row * DIMV + c16 * 8);
    }
    load_tile(0, 0);
    cp_commit();

    float l_acc = 0.0f;
    uint32_t phS = 0, phO = 0;
    const float scale = 0.03125f;
    int half = wid >> 2;
    int srow = (wid & 3) * 32 + lane;

    for (int jt = 0; jt < MV / 128; jt++) {
        int s = jt & 1;
        if (jt > 0) { mbar_wait(sb + 16, phO); phO ^= 1; }
        if (jt + 1 < MV / 128) {
            load_tile(jt + 1, s ^ 1);
            cp_commit();
            cp_wait<1>();
        } else {
            cp_wait<0>();
        }
        asm volatile("fence.proxy.async.shared::cta;" ::: "memory");
        __syncthreads();

        if (wid == 0) {
            if (elect_one_pred()) {
                uint32_t ks = db + AKS0 + (uint32_t)s * 32768u;
                uint64_t dQh = make_desc(db + AQ_HI);
                uint64_t dQl = make_desc(db + AQ_LO);
                uint64_t dKh = make_desc(ks);
                uint64_t dKl = make_desc(ks + 16384);
                #pragma unroll
                for (int k2 = 0; k2 < 4; k2++) {
                    uint32_t en = (k2 > 0);
                    mma_f16_ss(tmem, dQh + 2 * k2, dKh + 2 * k2, IDESC_S, en);
                    mma_f16_ss(tmem, dQh + 2 * k2, dKl + 2 * k2, IDESC_S, 1u);
                    mma_f16_ss(tmem, dQl + 2 * k2, dKh + 2 * k2, IDESC_S, 1u);
                }
                TC_COMMIT(sb + 8);
            }
        }
        mbar_wait(sb + 8, phS); phS ^= 1;
        TC_FENCE_AFTER();

        {
            uint32_t r0[32], r1[32];
            TC_LD_X32(r0, tmem + half * 64);
            TC_LD_X32(r1, tmem + half * 64 + 32);
            TC_WAIT_LD();
            float sum = 0.f;
            uint32_t rowoff = (uint32_t)srow * 128;
            char* pP = dbp + AP + half * 16384;
            #pragma unroll
            for (int g = 0; g < 8; g++) {
                float e0 = __expf(__uint_as_float(r0[g * 4 + 0]) * scale);
                float e1 = __expf(__uint_as_float(r0[g * 4 + 1]) * scale);
                float e2 = __expf(__uint_as_float(r0[g * 4 + 2]) * scale);
                float e3 = __expf(__uint_as_float(r0[g * 4 + 3]) * scale);
                sum += (e0 + e1) + (e2 + e3);
                bf162 pp[2] = {bf162(__float2bfloat16_rn(e0), __float2bfloat16_rn(e1)),
                               bf162(__float2bfloat16_rn(e2), __float2bfloat16_rn(e3))};
                uint32_t boff = rowoff + g * 8;
                uint32_t sw = boff ^ ((boff >> 3) & 0x70);
                *(uint2*)(pP + sw) = *(uint2*)pp;
            }
            #pragma unroll
            for (int g = 0; g < 8; g++) {
                float e0 = __expf(__uint_as_float(r1[g * 4 + 0]) * scale);
                float e1 = __expf(__uint_as_float(r1[g * 4 + 1]) * scale);
                float e2 = __expf(__uint_as_float(r1[g * 4 + 2]) * scale);
                float e3 = __expf(__uint_as_float(r1[g * 4 + 3]) * scale);
                sum += (e0 + e1) + (e2 + e3);
                bf162 pp[2] = {bf162(__float2bfloat16_rn(e0), __float2bfloat16_rn(e1)),
                               bf162(__float2bfloat16_rn(e2), __float2bfloat16_rn(e3))};
                uint32_t boff = rowoff + 64 + g * 8;
                uint32_t sw = boff ^ ((boff >> 3) & 0x70);
                *(uint2*)(pP + sw) = *(uint2*)pp;
            }
            l_acc += sum;
        }
        asm volatile("fence.proxy.async.shared::cta;" ::: "memory");
        __syncthreads();

        if (wid == 0) {
            if (elect_one_pred()) {
                uint32_t vs = db + AVS0 + (uint32_t)s * 32768u;
                #pragma unroll
                for (int ch = 0; ch < 2; ch++) {
                    uint64_t dP  = make_desc(db + AP + ch * 16384);
                    uint64_t dVh = make_desc(vs + ch * 8192);
                    uint64_t dVl = make_desc(vs + 16384 + ch * 8192);
                    #pragma unroll
                    for (int k2 = 0; k2 < 4; k2++) {
                        uint32_t en = (jt > 0) || (ch > 0) || (k2 > 0);
                        mma_f16_ss(tmem + 128, dP + 2 * k2, dVh + 2 * k2, IDESC_O, en);
                        mma_f16_ss(tmem + 128, dP + 2 * k2, dVl + 2 * k2, IDESC_O, 1u);
                    }
                }
                TC_COMMIT(sb + 16);
            }
        }
    }
    mbar_wait(sb + 16, phO);
    TC_FENCE_AFTER();

    *(float*)(dbp + AL_OFF + (half * 128 + srow) * 4) = l_acc;
    __syncthreads();

    if (tid < 128) {
        uint32_t r0[32], r1[32];
        TC_LD_X32(r0, tmem + 128);
        TC_LD_X32(r1, tmem + 160);
        TC_WAIT_LD();
        int row = wid * 32 + lane;
        float l = *(float*)(dbp + AL_OFF + row * 4) +
                  *(float*)(dbp + AL_OFF + (128 + row) * 4);
        float inv = 1.0f / l;
        size_t obase = ((size_t)(b * NV) + qt * 128 + row) * DIMV + h * DHEAD;
        #pragma unroll
        for (int g = 0; g < 8; g++) {
            float vv[4];
            vv[0] = __uint_as_float(r0[g * 4 + 0]) * inv;
            vv[1] = __uint_as_float(r0[g * 4 + 1]) * inv;
            vv[2] = __uint_as_float(r0[g * 4 + 2]) * inv;
            vv[3] = __uint_as_float(r0[g * 4 + 3]) * inv;
            bf162 h2[2], l2[2];
            bf16_split4(vv, h2, l2);
            *(uint2*)&ohi[obase + g * 4] = *(uint2*)h2;
            *(uint2*)&olo[obase + g * 4] = *(uint2*)l2;
        }
        #pragma unroll
        for (int g = 0; g < 8; g++) {
            float vv[4];
            vv[0] = __uint_as_float(r1[g * 4 + 0]) * inv;
            vv[1] = __uint_as_float(r1[g * 4 + 1]) * inv;
            vv[2] = __uint_as_float(r1[g * 4 + 2]) * inv;
            vv[3] = __uint_as_float(r1[g * 4 + 3]) * inv;
            bf162 h2[2], l2[2];
            bf16_split4(vv, h2, l2);
            *(uint2*)&ohi[obase + 32 + g * 4] = *(uint2*)h2;
            *(uint2*)&olo[obase + 32 + g * 4] = *(uint2*)l2;
        }
    }
    __syncthreads();
    if (wid == 0) { TC_DEALLOC(tmem, 256); }
#else
    int tid = threadIdx.x;
    if (tid >= 128) return;
    int qt = blockIdx.x, h = blockIdx.y, b = blockIdx.z;
    int row = qt * 128 + tid;
    size_t qb = ((size_t)(b * NV) + row) * DIMV + h * DHEAD;
    float o[64];
    #pragma unroll
    for (int d = 0; d < 64; d++) o[d] = 0.f;
    float l = 0.f;
    for (int j = 0; j < MV; j++) {
        size_t kb = ((size_t)(b * MV) + j) * KVSTR + h * DHEAD;
        float s = 0.f;
        for (int d = 0; d < 64; d++)
            s += (__bfloat162float(qhi[qb + d]) + __bfloat162float(qlo[qb + d])) *
                 (__bfloat162float(kvhi[kb + d]) + __bfloat162float(kvlo[kb + d]));
        float e = __expf(s * 0.03125f);
        l += e;
        size_t tok = (size_t)b * NV + j;
        for (int d = 0; d < 64; d++) {
            size_t vo = (size_t)(h * DHEAD + d) * ROWS + tok;
            o[d] += e * (__bfloat162float(vthi[vo]) + __bfloat162float(vtlo[vo]));
        }
    }
    float inv = 1.f / l;
    for (int d = 0; d < 64; d++) {
        bf16 hh, ll;
        bf16_split(o[d] * inv, hh, ll);
        ohi[qb + d] = hh;
        olo[qb + d] = ll;
    }
#endif
}

// ---------------------------------------------------------------------------
// Launch
// ---------------------------------------------------------------------------
static void launch_split(const float* x, bf16* hi, bf16* lo, size_t n) {
    int n4 = (int)(n / 4);
    split_kernel<<<(n4 + 255) / 256, 256>>>((const float4*)x, (bf162*)hi,
                                            (bf162*)lo, n4);
}
static void launch_tsplit(const float* W, bf16* Thi, bf16* Tlo, int K, int N) {
    dim3 g(N / 32, K / 32), b(32, 8);
    tsplit_kernel<<<g, b>>>(W, Thi, Tlo, K, N);
}

extern "C" void kernel_launch(void* const* d_in, const int* in_sizes, int n_in,
                              void* d_out, int out_size) {
    (void)in_sizes; (void)n_in; (void)out_size;
    const float* x_in  = (const float*)d_in[0];
    const float* m_in  = (const float*)d_in[1];
    const float* Wq    = (const float*)d_in[2];
    const float* Wk    = (const float*)d_in[3];
    const float* Wv    = (const float*)d_in[4];
    const float* Wo    = (const float*)d_in[5];
    const float* bo    = (const float*)d_in[6];
    const float* ln1w  = (const float*)d_in[7];
    const float* ln1b  = (const float*)d_in[8];
    const float* W1    = (const float*)d_in[9];
    const float* b1    = (const float*)d_in[10];
    const float* W2    = (const float*)d_in[11];
    const float* b2    = (const float*)d_in[12];
    const float* ln2w  = (const float*)d_in[13];
    const float* ln2b  = (const float*)d_in[14];

    float* x = (float*)d_out;

    void *qv_, *kv_, *vv_;
    bf16 *atthi, *attlo, *hhi, *hlo, *wth, *wtl, *ffhi, *fflo, *mhi, *mlo;
    cudaGetSymbolAddress(&qv_, g_q);
    cudaGetSymbolAddress(&kv_, g_k);
    cudaGetSymbolAddress(&vv_, g_v);
    cudaGetSymbolAddress((void**)&atthi, g_att_hi);
    cudaGetSymbolAddress((void**)&attlo, g_att_lo);
    cudaGetSymbolAddress((void**)&hhi,   g_h_hi);
    cudaGetSymbolAddress((void**)&hlo,   g_h_lo);
    cudaGetSymbolAddress((void**)&wth,   g_wt_hi);
    cudaGetSymbolAddress((void**)&wtl,   g_wt_lo);
    cudaGetSymbolAddress((void**)&ffhi,  g_ff_hi);
    cudaGetSymbolAddress((void**)&fflo,  g_ff_lo);
    cudaGetSymbolAddress((void**)&mhi,   g_m_hi);
    cudaGetSymbolAddress((void**)&mlo,   g_m_lo);

    bf16* qh  = (bf16*)qv_;  bf16* ql  = qh + (size_t)ROWS * DIMV;
    bf16* kvh = (bf16*)kv_;
    bf16* kvl = (bf16*)vv_;
    bf16* vth = ffhi;        // vt shares g_ff (attention finishes before W1)
    bf16* vtl = fflo;

    cudaFuncSetAttribute(gemm_bf16<0, 0, 1, 0>, cudaFuncAttributeMaxDynamicSharedMemorySize, GEMM_SMEM);
    cudaFuncSetAttribute(gemm_bf16<0, 0, 1, 1>, cudaFuncAttributeMaxDynamicSharedMemorySize, GEMM_SMEM);
    cudaFuncSetAttribute(gemm_bf16<0, 1, 0, 0>, cudaFuncAttributeMaxDynamicSharedMemorySize, GEMM_SMEM);
    cudaFuncSetAttribute(gemm_bf16<1, 0, 1, 0>, cudaFuncAttributeMaxDynamicSharedMemorySize, GEMM_SMEM);
    cudaFuncSetAttribute(attn_tc, cudaFuncAttributeMaxDynamicSharedMemorySize, ATTN_SMEM);

    cudaMemcpyAsync(x, x_in, (size_t)ROWS * DIMV * sizeof(float),
                    cudaMemcpyDeviceToDevice);

    launch_split(m_in, mhi, mlo, (size_t)ROWS * DIMV);   // once

    dim3 gp(DIMV / 128, ROWS / 128);       // 8 x 32
    dim3 gkv(KVSTR / 128, ROWS / 128);     // 16 x 32
    dim3 gmlp(MLPV / 128, ROWS / 128);     // 32 x 32
    dim3 gattn(NV / 128, HEADS, BV);       // 8 x 16 x 4

    for (int layer = 0; layer < DEPTH; layer++) {
        const float* Wq_l = Wq + (size_t)layer * DIMV * DIMV;
        const float* Wk_l = Wk + (size_t)layer * DIMV * DIMV;
        const float* Wv_l = Wv + (size_t)layer * DIMV * DIMV;
        const float* Wo_l = Wo + (size_t)layer * DIMV * DIMV;
        const float* bo_l = bo + (size_t)layer * DIMV;
        const float* W1_l = W1 + (size_t)layer * DIMV * MLPV;
        const float* b1_l = b1 + (size_t)layer * MLPV;
        const float* W2_l = W2 + (size_t)layer * MLPV * DIMV;
        const float* b2_l = b2 + (size_t)layer * DIMV;

        // --- cross-attention block ---
        ln_split_kernel<<<ROWS, 256>>>(x, ln1w + (size_t)layer * DIMV,
                                       ln1b + (size_t)layer * DIMV, hhi, hlo);

        launch_tsplit(Wq_l, wth, wtl, DIMV, DIMV);
        gemm_bf16<0, 0, 1, 0><<<gp, 256, GEMM_SMEM>>>(hhi, hlo, wth, wtl,
                                                      nullptr, nullptr, nullptr,
                                                      qh, ql, nullptr, nullptr,
                                                      DIMV, DIMV);
        launch_tsplit(Wk_l, wth, wtl, DIMV, DIMV);
        launch_tsplit(Wv_l, wth + (size_t)DIMV * DIMV,
                            wtl + (size_t)DIMV * DIMV, DIMV, DIMV);
        gemm_bf16<0, 0, 1, 1><<<gkv, 256, GEMM_SMEM>>>(mhi, mlo, wth, wtl,
                                                       nullptr, nullptr, nullptr,
                                                       kvh, kvl, vth, vtl,
                                                       DIMV, KVSTR);

        attn_tc<<<gattn, 256, ATTN_SMEM>>>(qh, ql, kvh, kvl, vth, vtl,
                                           atthi, attlo);

        launch_tsplit(Wo_l, wth, wtl, DIMV, DIMV);
        gemm_bf16<0, 1, 0, 0><<<gp, 256, GEMM_SMEM>>>(atthi, attlo, wth, wtl,
                                                      bo_l, x, x,
                                                      nullptr, nullptr, nullptr, nullptr,
                                                      DIMV, DIMV);

        // --- feed-forward block ---
        ln_split_kernel<<<ROWS, 256>>>(x, ln2w + (size_t)layer * DIMV,
                                       ln2b + (size_t)layer * DIMV, hhi, hlo);

        launch_tsplit(W1_l, wth, wtl, DIMV, MLPV);
        gemm_bf16<1, 0, 1, 0><<<gmlp, 256, GEMM_SMEM>>>(hhi, hlo, wth, wtl,
                                                        b1_l, nullptr, nullptr,
                                                        ffhi, fflo, nullptr, nullptr,
                                                        DIMV, MLPV);

        launch_tsplit(W2_l, wth, wtl, MLPV, DIMV);
        gemm_bf16<0, 1, 0, 0><<<gp, 256, GEMM_SMEM>>>(ffhi, fflo, wth, wtl,
                                                      b2_l, x, x,
                                                      nullptr, nullptr, nullptr, nullptr,
                                                      MLPV, DIMV);
    }
}

// round 17
// speedup vs baseline: 1.4152x; 1.4152x over previous
#include <cuda_runtime.h>
#include <cuda_bf16.h>
#include <math.h>
#include <stdint.h>

#if defined(__CUDA_ARCH_FEAT_SM103_ALL) || defined(__CUDA_ARCH_FEAT_SM100_ALL) || \
    (defined(__CUDA_ARCH_SPECIFIC__) && (__CUDA_ARCH_SPECIFIC__ >= 1000))
#define HAS_TC 1
#else
#define HAS_TC 0
#endif

#define DEPTH   4
#define HEADS   16
#define DIMV    1024
#define DHEAD   64
#define MLPV    4096
#define BV      4
#define NV      1024
#define MV      1024
#define ROWS    (BV * NV)
#define EPSV    1e-5f
#define KVSTR   2048

typedef __nv_bfloat16 bf16;
typedef __nv_bfloat162 bf162;

// ---------------------------------------------------------------------------
// Scratch
// ---------------------------------------------------------------------------
__device__ float g_q  [ROWS * DIMV];   // bf16 q_hi | q_lo
__device__ float g_k  [ROWS * DIMV];   // bf16 kv_hi (ROWS x 2048)
__device__ float g_v  [ROWS * DIMV];   // bf16 kv_lo (ROWS x 2048)
__device__ bf16  g_att_hi[ROWS * DIMV];
__device__ bf16  g_att_lo[ROWS * DIMV];
__device__ bf16  g_h_hi  [ROWS * DIMV];
__device__ bf16  g_h_lo  [ROWS * DIMV];
__device__ bf16  g_wt_hi [MLPV * DIMV];
__device__ bf16  g_wt_lo [MLPV * DIMV];
__device__ bf16  g_ff_hi [ROWS * MLPV];   // front 4M: vt_hi [1024 d][4096 tok]
__device__ bf16  g_ff_lo [ROWS * MLPV];   // front 4M: vt_lo
__device__ bf16  g_m_hi  [ROWS * DIMV];
__device__ bf16  g_m_lo  [ROWS * DIMV];

// ---------------------------------------------------------------------------
// PTX helpers
// ---------------------------------------------------------------------------
__device__ __forceinline__ uint32_t smem_u32(const void* p) {
    uint32_t a;
    asm("{ .reg .u64 t; cvta.to.shared.u64 t, %1; cvt.u32.u64 %0, t; }"
        : "=r"(a) : "l"(p));
    return a;
}

__device__ __forceinline__ uint32_t elect_one_pred() {
    uint32_t pred;
    asm volatile("{\n\t.reg .pred p;\n\t"
                 "elect.sync _|p, 0xFFFFFFFF;\n\t"
                 "selp.b32 %0, 1, 0, p;\n\t}"
                 : "=r"(pred));
    return pred;
}

__device__ __forceinline__ void cpasync16(uint32_t saddr, const void* g) {
    asm volatile("cp.async.cg.shared.global [%0], [%1], 16;\n"
                 :: "r"(saddr), "l"(g));
}
__device__ __forceinline__ void cp_commit() {
    asm volatile("cp.async.commit_group;\n" ::: "memory");
}
template <int N>
__device__ __forceinline__ void cp_wait() {
    asm volatile("cp.async.wait_group %0;\n" :: "n"(N) : "memory");
}

__device__ __forceinline__ void mbar_init(uint32_t addr, uint32_t cnt) {
    asm volatile("mbarrier.init.shared.b64 [%0], %1;" :: "r"(addr), "r"(cnt) : "memory");
}
__device__ __forceinline__ void mbar_wait(uint32_t addr, uint32_t parity) {
    uint32_t done;
    asm volatile("{\n\t.reg .pred p;\n\t"
                 "mbarrier.try_wait.parity.acquire.cta.shared::cta.b64 p, [%1], %2;\n\t"
                 "selp.b32 %0, 1, 0, p;\n\t}\n"
                 : "=r"(done) : "r"(addr), "r"(parity) : "memory");
    while (!done) {
        asm volatile("{\n\t.reg .pred p;\n\t"
                     "mbarrier.try_wait.parity.acquire.cta.shared::cta.b64 p, [%1], %2, 0x989680;\n\t"
                     "selp.b32 %0, 1, 0, p;\n\t}\n"
                     : "=r"(done) : "r"(addr), "r"(parity) : "memory");
    }
}

#if HAS_TC
__device__ __forceinline__ uint64_t make_desc(uint32_t addr) {
    const uint64_t base =
        (uint64_t(2)  << 61) | (uint64_t(1) << 46) |
        (uint64_t(64) << 32) | (uint64_t(1) << 16);
    return base | ((uint64_t)(addr >> 4) & 0x3FFF);
}

__device__ __forceinline__ void mma_f16_ss(uint32_t d_tmem, uint64_t a_desc,
                                           uint64_t b_desc, uint32_t idesc,
                                           uint32_t enable) {
    asm volatile("{\n\t.reg .pred p;\n\t"
                 "setp.ne.u32 p, %4, 0;\n\t"
                 "tcgen05.mma.cta_group::1.kind::f16 [%0], %1, %2, %3, "
                 "{%5, %5, %5, %5}, p;\n\t}"
                 :: "r"(d_tmem), "l"(a_desc), "l"(b_desc), "r"(idesc),
                    "r"(enable), "r"(0u)
                 : "memory");
}

#define TC_ALLOC(smem_addr, n) \
    asm volatile("tcgen05.alloc.cta_group::1.sync.aligned.shared::cta.b32 [%0], %1;" \
                 :: "r"(smem_addr), "r"((uint32_t)(n)) : "memory")
#define TC_RELINQ() \
    asm volatile("tcgen05.relinquish_alloc_permit.cta_group::1.sync.aligned;")
#define TC_DEALLOC(tmem, n) \
    asm volatile("tcgen05.dealloc.cta_group::1.sync.aligned.b32 %0, %1;" \
                 :: "r"(tmem), "r"((uint32_t)(n)))
#define TC_COMMIT(mbar) \
    asm volatile("tcgen05.commit.cta_group::1.mbarrier::arrive::one.shared::cluster.b64 [%0];" \
                 :: "r"(mbar) : "memory")
#define TC_FENCE_AFTER() \
    asm volatile("tcgen05.fence::after_thread_sync;" ::: "memory")
#define TC_WAIT_LD() \
    asm volatile("tcgen05.wait::ld.sync.aligned;" ::: "memory")

#define TC_LD_X32(r, addr) \
    asm volatile( \
        "tcgen05.ld.sync.aligned.32x32b.x32.b32 " \
        "{%0, %1, %2, %3, %4, %5, %6, %7, " \
        " %8, %9, %10, %11, %12, %13, %14, %15, " \
        " %16, %17, %18, %19, %20, %21, %22, %23, " \
        " %24, %25, %26, %27, %28, %29, %30, %31}, [%32];" \
        : "=r"((r)[0]),  "=r"((r)[1]),  "=r"((r)[2]),  "=r"((r)[3]), \
          "=r"((r)[4]),  "=r"((r)[5]),  "=r"((r)[6]),  "=r"((r)[7]), \
          "=r"((r)[8]),  "=r"((r)[9]),  "=r"((r)[10]), "=r"((r)[11]), \
          "=r"((r)[12]), "=r"((r)[13]), "=r"((r)[14]), "=r"((r)[15]), \
          "=r"((r)[16]), "=r"((r)[17]), "=r"((r)[18]), "=r"((r)[19]), \
          "=r"((r)[20]), "=r"((r)[21]), "=r"((r)[22]), "=r"((r)[23]), \
          "=r"((r)[24]), "=r"((r)[25]), "=r"((r)[26]), "=r"((r)[27]), \
          "=r"((r)[28]), "=r"((r)[29]), "=r"((r)[30]), "=r"((r)[31]) \
        : "r"(addr))
#endif  // HAS_TC

// ---------------------------------------------------------------------------
// splits
// ---------------------------------------------------------------------------
__device__ __forceinline__ void bf16_split(float v, bf16& hi, bf16& lo) {
    hi = __float2bfloat16_rn(v);
    lo = __float2bfloat16_rn(v - __bfloat162float(hi));
}

__device__ __forceinline__ void bf16_split4(const float* v, bf162* h2, bf162* l2) {
    bf16 h[4], l[4];
    #pragma unroll
    for (int i = 0; i < 4; i++) bf16_split(v[i], h[i], l[i]);
    h2[0] = bf162(h[0], h[1]); h2[1] = bf162(h[2], h[3]);
    l2[0] = bf162(l[0], l[1]); l2[1] = bf162(l[2], l[3]);
}

__global__ void split_kernel(const float4* __restrict__ x,
                             bf162* __restrict__ hi, bf162* __restrict__ lo,
                             int n4) {
    int i = blockIdx.x * 256 + threadIdx.x;
    if (i >= n4) return;
    float4 v = x[i];
    float vv[4] = {v.x, v.y, v.z, v.w};
    bf162 h2[2], l2[2];
    bf16_split4(vv, h2, l2);
    hi[i * 2] = h2[0]; hi[i * 2 + 1] = h2[1];
    lo[i * 2] = l2[0]; lo[i * 2 + 1] = l2[1];
}

// transpose + split: W[K,N] fp32 -> Thi/Tlo [N,K] bf16
__global__ void tsplit_kernel(const float* __restrict__ W,
                              bf16* __restrict__ Thi, bf16* __restrict__ Tlo,
                              int K, int N) {
    __shared__ float tile[32][33];
    int n0 = blockIdx.x * 32, k0 = blockIdx.y * 32;
    int tx = threadIdx.x, ty = threadIdx.y;   // 32 x 8
    #pragma unroll
    for (int i = 0; i < 32; i += 8)
        tile[ty + i][tx] = W[(size_t)(k0 + ty + i) * N + n0 + tx];
    __syncthreads();
    #pragma unroll
    for (int i = 0; i < 32; i += 8) {
        float v = tile[tx][ty + i];
        bf16 h, l;
        bf16_split(v, h, l);
        size_t o = (size_t)(n0 + ty + i) * K + k0 + tx;
        Thi[o] = h; Tlo[o] = l;
    }
}

// ---------------------------------------------------------------------------
// GEMM (3xBF16): C[M,N] = A @ W. Tile 128x128, single 64KB stage,
// serial load->MMA per chunk; occupancy 3 CTAs/SM provides the overlap
// (alloc permit relinquished right after alloc so CTAs co-reside).
// ---------------------------------------------------------------------------
#define GEMM_SMEM (65536 + 2048)
#define IDESC_BF16 ((1u << 4) | (1u << 7) | (1u << 10) | ((128u / 8) << 17) | ((128u / 16) << 24))

__device__ __forceinline__ void load_tile128x64(uint32_t sbase,
                                                const bf16* __restrict__ g,
                                                int ld) {
    int t = threadIdx.x;
    #pragma unroll
    for (int i = 0; i < 4; i++) {
        int e = i * 256 + t;
        int row = e >> 3, c16 = e & 7;
        uint32_t boff = row * 128 + c16 * 16;
        uint32_t sw = boff ^ ((boff >> 3) & 0x70);
        cpasync16(sbase + sw, g + (size_t)row * ld + c16 * 8);
    }
}

template <int DO_GELU, int DO_RES, int DO_SPLIT, int DO_VT>
__global__ void __launch_bounds__(256)
gemm_bf16(const bf16* __restrict__ Ahi, const bf16* __restrict__ Alo,
          const bf16* __restrict__ Bhi, const bf16* __restrict__ Blo,
          const float* __restrict__ bias, const float* __restrict__ R,
          float* __restrict__ C, bf16* __restrict__ Chi, bf16* __restrict__ Clo,
          bf16* __restrict__ Vthi, bf16* __restrict__ Vtlo,
          int K, int Nc) {
#if HAS_TC
    extern __shared__ char smem[];
    uint32_t sb = smem_u32(smem);
    uint32_t db = (sb + 32 + 1023u) & ~1023u;
    int tid = threadIdx.x;
    int wid = tid >> 5;

    if (wid == 0) { TC_ALLOC(sb + 0, 128); TC_RELINQ(); }
    if (tid == 0) { mbar_init(sb + 8, 1); }
    __syncthreads();
    uint32_t tmem;
    asm volatile("ld.shared.b32 %0, [%1];" : "=r"(tmem) : "r"(sb + 0));

    int m0 = blockIdx.y * 128;
    int n0 = blockIdx.x * 128;
    const bf16* aH = Ahi + (size_t)m0 * K;
    const bf16* aL = Alo + (size_t)m0 * K;
    const bf16* bH = Bhi + (size_t)n0 * K;
    const bf16* bL = Blo + (size_t)n0 * K;

    const int CH = K / 64;
    uint32_t ph = 0;

    for (int c = 0; c < CH; c++) {
        if (c > 0) { mbar_wait(sb + 8, ph); ph ^= 1; }   // MMA(c-1) done
        int kc = c * 64;
        load_tile128x64(db,         aH + kc, K);
        load_tile128x64(db + 16384, aL + kc, K);
        load_tile128x64(db + 32768, bH + kc, K);
        load_tile128x64(db + 49152, bL + kc, K);
        cp_commit();
        cp_wait<0>();
        asm volatile("fence.proxy.async.shared::cta;" ::: "memory");
        __syncthreads();
        if (wid == 0) {
            if (elect_one_pred()) {
                uint64_t dAh = make_desc(db);
                uint64_t dAl = make_desc(db + 16384);
                uint64_t dBh = make_desc(db + 32768);
                uint64_t dBl = make_desc(db + 49152);
                #pragma unroll
                for (int k = 0; k < 4; k++) {
                    uint32_t en = (c > 0) || (k > 0);
                    mma_f16_ss(tmem, dAh + 2 * k, dBh + 2 * k, IDESC_BF16, en);
                    mma_f16_ss(tmem, dAh + 2 * k, dBl + 2 * k, IDESC_BF16, 1u);
                    mma_f16_ss(tmem, dAl + 2 * k, dBh + 2 * k, IDESC_BF16, 1u);
                }
                TC_COMMIT(sb + 8);
            }
        }
    }
    mbar_wait(sb + 8, ph);
    TC_FENCE_AFTER();

    if (wid < 4) {
        int lane = tid & 31;
        int row = m0 + wid * 32 + lane;
        #pragma unroll
        for (int b4 = 0; b4 < 4; b4++) {
            uint32_t r[32];
            TC_LD_X32(r, tmem + b4 * 32);
            TC_WAIT_LD();
            float vals[32];
            #pragma unroll
            for (int j = 0; j < 32; j++) {
                float v = __uint_as_float(r[j]);
                int col = n0 + b4 * 32 + j;
                if (bias) v += bias[col];
                if (DO_GELU) v = 0.5f * v * (1.0f + erff(v * 0.70710678118654752f));
                if (DO_RES) v += R[(size_t)row * Nc + col];
                vals[j] = v;
            }
            if (DO_VT && (n0 + b4 * 32) >= DIMV) {
                #pragma unroll
                for (int j = 0; j < 32; j++) {
                    int d = n0 + b4 * 32 + j - DIMV;
                    bf16 hh, ll;
                    bf16_split(vals[j], hh, ll);
                    Vthi[(size_t)d * ROWS + row] = hh;
                    Vtlo[(size_t)d * ROWS + row] = ll;
                }
            } else if (DO_SPLIT) {
                #pragma unroll
                for (int j4 = 0; j4 < 8; j4++) {
                    bf162 h2[2], l2[2];
                    bf16_split4(&vals[j4 * 4], h2, l2);
                    size_t o = (size_t)row * Nc + n0 + b4 * 32 + j4 * 4;
                    *(uint2*)&Chi[o] = *(uint2*)h2;
                    *(uint2*)&Clo[o] = *(uint2*)l2;
                }
            } else {
                #pragma unroll
                for (int j4 = 0; j4 < 8; j4++) {
                    *(float4*)&C[(size_t)row * Nc + n0 + b4 * 32 + j4 * 4] =
                        make_float4(vals[j4*4], vals[j4*4+1],
                                    vals[j4*4+2], vals[j4*4+3]);
                }
            }
        }
    }
    __syncthreads();
    if (wid == 0) { TC_DEALLOC(tmem, 128); }
#else
    // ---- scalar fallback (plain sm_103 pass only) ----
    extern __shared__ char smem[];
    float* As = (float*)smem;
    float* Bs = As + 16 * 128;
    int tid = threadIdx.x;
    int tx = tid & 15, ty = tid >> 4;
    int m0 = blockIdx.y * 128;
    int n0 = blockIdx.x * 128;

    float acc[8][8];
    #pragma unroll
    for (int i = 0; i < 8; i++)
        #pragma unroll
        for (int j = 0; j < 8; j++) acc[i][j] = 0.f;

    for (int k0 = 0; k0 < K; k0 += 16) {
        __syncthreads();
        #pragma unroll
        for (int e = 0; e < 8; e++) {
            int idx = e * 256 + tid;
            int rr = idx >> 4, kk = idx & 15;
            As[kk * 128 + rr] =
                __bfloat162float(Ahi[(size_t)(m0 + rr) * K + k0 + kk]) +
                __bfloat162float(Alo[(size_t)(m0 + rr) * K + k0 + kk]);
            Bs[kk * 128 + rr] =
                __bfloat162float(Bhi[(size_t)(n0 + rr) * K + k0 + kk]) +
                __bfloat162float(Blo[(size_t)(n0 + rr) * K + k0 + kk]);
        }
        __syncthreads();
        #pragma unroll
        for (int k = 0; k < 16; k++) {
            float ar[8], br[8];
            #pragma unroll
            for (int i = 0; i < 8; i++) ar[i] = As[k * 128 + ty * 8 + i];
            #pragma unroll
            for (int j = 0; j < 8; j++) br[j] = Bs[k * 128 + tx * 8 + j];
            #pragma unroll
            for (int i = 0; i < 8; i++)
                #pragma unroll
                for (int j = 0; j < 8; j++)
                    acc[i][j] += ar[i] * br[j];
        }
    }
    #pragma unroll
    for (int i = 0; i < 8; i++) {
        int row = m0 + ty * 8 + i;
        #pragma unroll
        for (int j = 0; j < 8; j++) {
            int col = n0 + tx * 8 + j;
            float v = acc[i][j];
            if (bias) v += bias[col];
            if (DO_GELU) v = 0.5f * v * (1.0f + erff(v * 0.70710678118654752f));
            size_t idx = (size_t)row * Nc + col;
            if (DO_VT && col >= DIMV) {
                bf16 hh, ll;
                bf16_split(v, hh, ll);
                Vthi[(size_t)(col - DIMV) * ROWS + row] = hh;
                Vtlo[(size_t)(col - DIMV) * ROWS + row] = ll;
            } else if (DO_SPLIT) {
                bf16 hh, ll;
                bf16_split(v, hh, ll);
                Chi[idx] = hh; Clo[idx] = ll;
            } else {
                if (DO_RES) v += R[idx];
                C[idx] = v;
            }
        }
    }
#endif
}

// ---------------------------------------------------------------------------
// LayerNorm with fused bf16 split output
// ---------------------------------------------------------------------------
__global__ void ln_split_kernel(const float* __restrict__ x,
                                const float* __restrict__ w,
                                const float* __restrict__ b,
                                bf16* __restrict__ yhi,
                                bf16* __restrict__ ylo) {
    int row = blockIdx.x;
    int t   = threadIdx.x;
    const float4* xr = (const float4*)(x + (size_t)row * DIMV);
    float4 xv = xr[t];

    float s = xv.x + xv.y + xv.z + xv.w;
    float q = xv.x * xv.x + xv.y * xv.y + xv.z * xv.z + xv.w * xv.w;
    #pragma unroll
    for (int off = 16; off; off >>= 1) {
        s += __shfl_xor_sync(0xffffffffu, s, off);
        q += __shfl_xor_sync(0xffffffffu, q, off);
    }
    __shared__ float ss[8], sq[8];
    int wid = t >> 5, lane = t & 31;
    if (lane == 0) { ss[wid] = s; sq[wid] = q; }
    __syncthreads();
    if (t == 0) {
        float S = 0.f, Q = 0.f;
        #pragma unroll
        for (int i = 0; i < 8; i++) { S += ss[i]; Q += sq[i]; }
        ss[0] = S; sq[0] = Q;
    }
    __syncthreads();
    float mu   = ss[0] * (1.0f / DIMV);
    float var  = sq[0] * (1.0f / DIMV) - mu * mu;
    float rstd = rsqrtf(var + EPSV);

    float4 wv = ((const float4*)w)[t];
    float4 bv = ((const float4*)b)[t];
    float o[4];
    o[0] = (xv.x - mu) * rstd * wv.x + bv.x;
    o[1] = (xv.y - mu) * rstd * wv.y + bv.y;
    o[2] = (xv.z - mu) * rstd * wv.z + bv.z;
    o[3] = (xv.w - mu) * rstd * wv.w + bv.w;
    bf162 h2[2], l2[2];
    bf16_split4(o, h2, l2);
    size_t oo = (size_t)row * DIMV + t * 4;
    *(uint2*)&yhi[oo] = *(uint2*)h2;
    *(uint2*)&ylo[oo] = *(uint2*)l2;
}

// ---------------------------------------------------------------------------
// Tensor-core flash attention (round-15 body + permit relinquish)
// ---------------------------------------------------------------------------
#define AQ_HI  0
#define AQ_LO  16384
#define AKS0   32768
#define AVS0   98304
#define AP     163840
#define AL_OFF 196608
#define ATTN_SMEM (197632 + 2048)

#define IDESC_S ((1u << 4) | (1u << 7) | (1u << 10) | ((128u / 8) << 17) | ((128u / 16) << 24))
#define IDESC_O ((1u << 4) | (1u << 7) | (1u << 10) | ((64u  / 8) << 17) | ((128u / 16) << 24))

__global__ void __launch_bounds__(256)
attn_tc(const bf16* __restrict__ qhi, const bf16* __restrict__ qlo,
        const bf16* __restrict__ kvhi, const bf16* __restrict__ kvlo,
        const bf16* __restrict__ vthi, const bf16* __restrict__ vtlo,
        bf16* __restrict__ ohi, bf16* __restrict__ olo) {
#if HAS_TC
    extern __shared__ char smem[];
    uint32_t sb = smem_u32(smem);
    uint32_t db = (sb + 32 + 1023u) & ~1023u;
    char* dbp = smem + (db - sb);
    int tid = threadIdx.x;
    int wid = tid >> 5;
    int lane = tid & 31;
    int qt = blockIdx.x, h = blockIdx.y, b = blockIdx.z;

    if (wid == 0) { TC_ALLOC(sb + 0, 256); TC_RELINQ(); }
    if (tid == 0) { mbar_init(sb + 8, 1); mbar_init(sb + 16, 1); }
    __syncthreads();
    uint32_t tmem;
    asm volatile("ld.shared.b32 %0, [%1];" : "=r"(tmem) : "r"(sb + 0));

    auto load_tile = [&](int jt2, int s) {
        uint32_t ks = db + AKS0 + (uint32_t)s * 32768u;
        uint32_t vs = db + AVS0 + (uint32_t)s * 32768u;
        const size_t kb = ((size_t)(b * MV) + jt2 * 128) * KVSTR + h * DHEAD;
        #pragma unroll
        for (int i = 0; i < 4; i++) {
            int e = i * 256 + tid;
            int row = e >> 3, c16 = e & 7;
            uint32_t boff = row * 128 + c16 * 16;
            uint32_t sw = boff ^ ((boff >> 3) & 0x70);
            cpasync16(ks + sw,         kvhi + kb + (size_t)row * KVSTR + c16 * 8);
            cpasync16(ks + 16384 + sw, kvlo + kb + (size_t)row * KVSTR + c16 * 8);
        }
        const size_t vtb = (size_t)(h * DHEAD) * ROWS + (size_t)b * NV + jt2 * 128;
        #pragma unroll
        for (int i = 0; i < 4; i++) {
            int e = i * 256 + tid;
            int d = e >> 4, ch = (e >> 3) & 1, k8 = e & 7;
            uint32_t boff = d * 128 + k8 * 16;
            uint32_t sw = boff ^ ((boff >> 3) & 0x70);
            size_t src = vtb + (size_t)d * ROWS + ch * 64 + k8 * 8;
            cpasync16(vs + ch * 8192 + sw,         vthi + src);
            cpasync16(vs + 16384 + ch * 8192 + sw, vtlo + src);
        }
    };

    const size_t qb = ((size_t)(b * NV) + qt * 128) * DIMV + h * DHEAD;
    #pragma unroll
    for (int i = 0; i < 4; i++) {
        int e = i * 256 + tid;
        int row = e >> 3, c16 = e & 7;
        uint32_t boff = row * 128 + c16 * 16;
        uint32_t sw = boff ^ ((boff >> 3) & 0x70);
        cpasync16(db + AQ_HI + sw, qhi + qb + (size_t)row * DIMV + c16 * 8);
        cpasync16(db + AQ_LO + sw, qlo + qb + (size_t)row * DIMV + c16 * 8);
    }
    load_tile(0, 0);
    cp_commit();

    float l_acc = 0.0f;
    uint32_t phS = 0, phO = 0;
    const float scale = 0.03125f;
    int half = wid >> 2;
    int srow = (wid & 3) * 32 + lane;

    for (int jt = 0; jt < MV / 128; jt++) {
        int s = jt & 1;
        if (jt > 0) { mbar_wait(sb + 16, phO); phO ^= 1; }
        if (jt + 1 < MV / 128) {
            load_tile(jt + 1, s ^ 1);
            cp_commit();
            cp_wait<1>();
        } else {
            cp_wait<0>();
        }
        asm volatile("fence.proxy.async.shared::cta;" ::: "memory");
        __syncthreads();

        if (wid == 0) {
            if (elect_one_pred()) {
                uint32_t ks = db + AKS0 + (uint32_t)s * 32768u;
                uint64_t dQh = make_desc(db + AQ_HI);
                uint64_t dQl = make_desc(db + AQ_LO);
                uint64_t dKh = make_desc(ks);
                uint64_t dKl = make_desc(ks + 16384);
                #pragma unroll
                for (int k2 = 0; k2 < 4; k2++) {
                    uint32_t en = (k2 > 0);
                    mma_f16_ss(tmem, dQh + 2 * k2, dKh + 2 * k2, IDESC_S, en);
                    mma_f16_ss(tmem, dQh + 2 * k2, dKl + 2 * k2, IDESC_S, 1u);
                    mma_f16_ss(tmem, dQl + 2 * k2, dKh + 2 * k2, IDESC_S, 1u);
                }
                TC_COMMIT(sb + 8);
            }
        }
        mbar_wait(sb + 8, phS); phS ^= 1;
        TC_FENCE_AFTER();

        {
            uint32_t r0[32], r1[32];
            TC_LD_X32(r0, tmem + half * 64);
            TC_LD_X32(r1, tmem + half * 64 + 32);
            TC_WAIT_LD();
            float sum = 0.f;
            uint32_t rowoff = (uint32_t)srow * 128;
            char* pP = dbp + AP + half * 16384;
            #pragma unroll
            for (int g = 0; g < 8; g++) {
                float e0 = __expf(__uint_as_float(r0[g * 4 + 0]) * scale);
                float e1 = __expf(__uint_as_float(r0[g * 4 + 1]) * scale);
                float e2 = __expf(__uint_as_float(r0[g * 4 + 2]) * scale);
                float e3 = __expf(__uint_as_float(r0[g * 4 + 3]) * scale);
                sum += (e0 + e1) + (e2 + e3);
                bf162 pp[2] = {bf162(__float2bfloat16_rn(e0), __float2bfloat16_rn(e1)),
                               bf162(__float2bfloat16_rn(e2), __float2bfloat16_rn(e3))};
                uint32_t boff = rowoff + g * 8;
                uint32_t sw = boff ^ ((boff >> 3) & 0x70);
                *(uint2*)(pP + sw) = *(uint2*)pp;
            }
            #pragma unroll
            for (int g = 0; g < 8; g++) {
                float e0 = __expf(__uint_as_float(r1[g * 4 + 0]) * scale);
                float e1 = __expf(__uint_as_float(r1[g * 4 + 1]) * scale);
                float e2 = __expf(__uint_as_float(r1[g * 4 + 2]) * scale);
                float e3 = __expf(__uint_as_float(r1[g * 4 + 3]) * scale);
                sum += (e0 + e1) + (e2 + e3);
                bf162 pp[2] = {bf162(__float2bfloat16_rn(e0), __float2bfloat16_rn(e1)),
                               bf162(__float2bfloat16_rn(e2), __float2bfloat16_rn(e3))};
                uint32_t boff = rowoff + 64 + g * 8;
                uint32_t sw = boff ^ ((boff >> 3) & 0x70);
                *(uint2*)(pP + sw) = *(uint2*)pp;
            }
            l_acc += sum;
        }
        asm volatile("fence.proxy.async.shared::cta;" ::: "memory");
        __syncthreads();

        if (wid == 0) {
            if (elect_one_pred()) {
                uint32_t vs = db + AVS0 + (uint32_t)s * 32768u;
                #pragma unroll
                for (int ch = 0; ch < 2; ch++) {
                    uint64_t dP  = make_desc(db + AP + ch * 16384);
                    uint64_t dVh = make_desc(vs + ch * 8192);
                    uint64_t dVl = make_desc(vs + 16384 + ch * 8192);
                    #pragma unroll
                    for (int k2 = 0; k2 < 4; k2++) {
                        uint32_t en = (jt > 0) || (ch > 0) || (k2 > 0);
                        mma_f16_ss(tmem + 128, dP + 2 * k2, dVh + 2 * k2, IDESC_O, en);
                        mma_f16_ss(tmem + 128, dP + 2 * k2, dVl + 2 * k2, IDESC_O, 1u);
                    }
                }
                TC_COMMIT(sb + 16);
            }
        }
    }
    mbar_wait(sb + 16, phO);
    TC_FENCE_AFTER();

    *(float*)(dbp + AL_OFF + (half * 128 + srow) * 4) = l_acc;
    __syncthreads();

    if (tid < 128) {
        uint32_t r0[32], r1[32];
        TC_LD_X32(r0, tmem + 128);
        TC_LD_X32(r1, tmem + 160);
        TC_WAIT_LD();
        int row = wid * 32 + lane;
        float l = *(float*)(dbp + AL_OFF + row * 4) +
                  *(float*)(dbp + AL_OFF + (128 + row) * 4);
        float inv = 1.0f / l;
        size_t obase = ((size_t)(b * NV) + qt * 128 + row) * DIMV + h * DHEAD;
        #pragma unroll
        for (int g = 0; g < 8; g++) {
            float vv[4];
            vv[0] = __uint_as_float(r0[g * 4 + 0]) * inv;
            vv[1] = __uint_as_float(r0[g * 4 + 1]) * inv;
            vv[2] = __uint_as_float(r0[g * 4 + 2]) * inv;
            vv[3] = __uint_as_float(r0[g * 4 + 3]) * inv;
            bf162 h2[2], l2[2];
            bf16_split4(vv, h2, l2);
            *(uint2*)&ohi[obase + g * 4] = *(uint2*)h2;
            *(uint2*)&olo[obase + g * 4] = *(uint2*)l2;
        }
        #pragma unroll
        for (int g = 0; g < 8; g++) {
            float vv[4];
            vv[0] = __uint_as_float(r1[g * 4 + 0]) * inv;
            vv[1] = __uint_as_float(r1[g * 4 + 1]) * inv;
            vv[2] = __uint_as_float(r1[g * 4 + 2]) * inv;
            vv[3] = __uint_as_float(r1[g * 4 + 3]) * inv;
            bf162 h2[2], l2[2];
            bf16_split4(vv, h2, l2);
            *(uint2*)&ohi[obase + 32 + g * 4] = *(uint2*)h2;
            *(uint2*)&olo[obase + 32 + g * 4] = *(uint2*)l2;
        }
    }
    __syncthreads();
    if (wid == 0) { TC_DEALLOC(tmem, 256); }
#else
    int tid = threadIdx.x;
    if (tid >= 128) return;
    int qt = blockIdx.x, h = blockIdx.y, b = blockIdx.z;
    int row = qt * 128 + tid;
    size_t qb = ((size_t)(b * NV) + row) * DIMV + h * DHEAD;
    float o[64];
    #pragma unroll
    for (int d = 0; d < 64; d++) o[d] = 0.f;
    float l = 0.f;
    for (int j = 0; j < MV; j++) {
        size_t kb = ((size_t)(b * MV) + j) * KVSTR + h * DHEAD;
        float s = 0.f;
        for (int d = 0; d < 64; d++)
            s += (__bfloat162float(qhi[qb + d]) + __bfloat162float(qlo[qb + d])) *
                 (__bfloat162float(kvhi[kb + d]) + __bfloat162float(kvlo[kb + d]));
        float e = __expf(s * 0.03125f);
        l += e;
        size_t tok = (size_t)b * NV + j;
        for (int d = 0; d < 64; d++) {
            size_t vo = (size_t)(h * DHEAD + d) * ROWS + tok;
            o[d] += e * (__bfloat162float(vthi[vo]) + __bfloat162float(vtlo[vo]));
        }
    }
    float inv = 1.f / l;
    for (int d = 0; d < 64; d++) {
        bf16 hh, ll;
        bf16_split(o[d] * inv, hh, ll);
        ohi[qb + d] = hh;
        olo[qb + d] = ll;
    }
#endif
}

// ---------------------------------------------------------------------------
// Launch
// ---------------------------------------------------------------------------
static void launch_split(const float* x, bf16* hi, bf16* lo, size_t n) {
    int n4 = (int)(n / 4);
    split_kernel<<<(n4 + 255) / 256, 256>>>((const float4*)x, (bf162*)hi,
                                            (bf162*)lo, n4);
}
static void launch_tsplit(const float* W, bf16* Thi, bf16* Tlo, int K, int N) {
    dim3 g(N / 32, K / 32), b(32, 8);
    tsplit_kernel<<<g, b>>>(W, Thi, Tlo, K, N);
}

extern "C" void kernel_launch(void* const* d_in, const int* in_sizes, int n_in,
                              void* d_out, int out_size) {
    (void)in_sizes; (void)n_in; (void)out_size;
    const float* x_in  = (const float*)d_in[0];
    const float* m_in  = (const float*)d_in[1];
    const float* Wq    = (const float*)d_in[2];
    const float* Wk    = (const float*)d_in[3];
    const float* Wv    = (const float*)d_in[4];
    const float* Wo    = (const float*)d_in[5];
    const float* bo    = (const float*)d_in[6];
    const float* ln1w  = (const float*)d_in[7];
    const float* ln1b  = (const float*)d_in[8];
    const float* W1    = (const float*)d_in[9];
    const float* b1    = (const float*)d_in[10];
    const float* W2    = (const float*)d_in[11];
    const float* b2    = (const float*)d_in[12];
    const float* ln2w  = (const float*)d_in[13];
    const float* ln2b  = (const float*)d_in[14];

    float* x = (float*)d_out;

    void *qv_, *kv_, *vv_;
    bf16 *atthi, *attlo, *hhi, *hlo, *wth, *wtl, *ffhi, *fflo, *mhi, *mlo;
    cudaGetSymbolAddress(&qv_, g_q);
    cudaGetSymbolAddress(&kv_, g_k);
    cudaGetSymbolAddress(&vv_, g_v);
    cudaGetSymbolAddress((void**)&atthi, g_att_hi);
    cudaGetSymbolAddress((void**)&attlo, g_att_lo);
    cudaGetSymbolAddress((void**)&hhi,   g_h_hi);
    cudaGetSymbolAddress((void**)&hlo,   g_h_lo);
    cudaGetSymbolAddress((void**)&wth,   g_wt_hi);
    cudaGetSymbolAddress((void**)&wtl,   g_wt_lo);
    cudaGetSymbolAddress((void**)&ffhi,  g_ff_hi);
    cudaGetSymbolAddress((void**)&fflo,  g_ff_lo);
    cudaGetSymbolAddress((void**)&mhi,   g_m_hi);
    cudaGetSymbolAddress((void**)&mlo,   g_m_lo);

    bf16* qh  = (bf16*)qv_;  bf16* ql  = qh + (size_t)ROWS * DIMV;
    bf16* kvh = (bf16*)kv_;
    bf16* kvl = (bf16*)vv_;
    bf16* vth = ffhi;        // vt shares g_ff (attention finishes before W1)
    bf16* vtl = fflo;

    cudaFuncSetAttribute(gemm_bf16<0, 0, 1, 0>, cudaFuncAttributeMaxDynamicSharedMemorySize, GEMM_SMEM);
    cudaFuncSetAttribute(gemm_bf16<0, 0, 1, 1>, cudaFuncAttributeMaxDynamicSharedMemorySize, GEMM_SMEM);
    cudaFuncSetAttribute(gemm_bf16<0, 1, 0, 0>, cudaFuncAttributeMaxDynamicSharedMemorySize, GEMM_SMEM);
    cudaFuncSetAttribute(gemm_bf16<1, 0, 1, 0>, cudaFuncAttributeMaxDynamicSharedMemorySize, GEMM_SMEM);
    cudaFuncSetAttribute(attn_tc, cudaFuncAttributeMaxDynamicSharedMemorySize, ATTN_SMEM);

    cudaMemcpyAsync(x, x_in, (size_t)ROWS * DIMV * sizeof(float),
                    cudaMemcpyDeviceToDevice);

    launch_split(m_in, mhi, mlo, (size_t)ROWS * DIMV);   // once

    dim3 gp(DIMV / 128, ROWS / 128);       // 8 x 32
    dim3 gkv(KVSTR / 128, ROWS / 128);     // 16 x 32
    dim3 gmlp(MLPV / 128, ROWS / 128);     // 32 x 32
    dim3 gattn(NV / 128, HEADS, BV);       // 8 x 16 x 4

    for (int layer = 0; layer < DEPTH; layer++) {
        const float* Wq_l = Wq + (size_t)layer * DIMV * DIMV;
        const float* Wk_l = Wk + (size_t)layer * DIMV * DIMV;
        const float* Wv_l = Wv + (size_t)layer * DIMV * DIMV;
        const float* Wo_l = Wo + (size_t)layer * DIMV * DIMV;
        const float* bo_l = bo + (size_t)layer * DIMV;
        const float* W1_l = W1 + (size_t)layer * DIMV * MLPV;
        const float* b1_l = b1 + (size_t)layer * MLPV;
        const float* W2_l = W2 + (size_t)layer * MLPV * DIMV;
        const float* b2_l = b2 + (size_t)layer * DIMV;

        // --- cross-attention block ---
        ln_split_kernel<<<ROWS, 256>>>(x, ln1w + (size_t)layer * DIMV,
                                       ln1b + (size_t)layer * DIMV, hhi, hlo);

        launch_tsplit(Wq_l, wth, wtl, DIMV, DIMV);
        gemm_bf16<0, 0, 1, 0><<<gp, 256, GEMM_SMEM>>>(hhi, hlo, wth, wtl,
                                                      nullptr, nullptr, nullptr,
                                                      qh, ql, nullptr, nullptr,
                                                      DIMV, DIMV);
        launch_tsplit(Wk_l, wth, wtl, DIMV, DIMV);
        launch_tsplit(Wv_l, wth + (size_t)DIMV * DIMV,
                            wtl + (size_t)DIMV * DIMV, DIMV, DIMV);
        gemm_bf16<0, 0, 1, 1><<<gkv, 256, GEMM_SMEM>>>(mhi, mlo, wth, wtl,
                                                       nullptr, nullptr, nullptr,
                                                       kvh, kvl, vth, vtl,
                                                       DIMV, KVSTR);

        attn_tc<<<gattn, 256, ATTN_SMEM>>>(qh, ql, kvh, kvl, vth, vtl,
                                           atthi, attlo);

        launch_tsplit(Wo_l, wth, wtl, DIMV, DIMV);
        gemm_bf16<0, 1, 0, 0><<<gp, 256, GEMM_SMEM>>>(atthi, attlo, wth, wtl,
                                                      bo_l, x, x,
                                                      nullptr, nullptr, nullptr, nullptr,
                                                      DIMV, DIMV);

        // --- feed-forward block ---
        ln_split_kernel<<<ROWS, 256>>>(x, ln2w + (size_t)layer * DIMV,
                                       ln2b + (size_t)layer * DIMV, hhi, hlo);

        launch_tsplit(W1_l, wth, wtl, DIMV, MLPV);
        gemm_bf16<1, 0, 1, 0><<<gmlp, 256, GEMM_SMEM>>>(hhi, hlo, wth, wtl,
                                                        b1_l, nullptr, nullptr,
                                                        ffhi, fflo, nullptr, nullptr,
                                                        DIMV, MLPV);

        launch_tsplit(W2_l, wth, wtl, MLPV, DIMV);
        gemm_bf16<0, 1, 0, 0><<<gp, 256, GEMM_SMEM>>>(ffhi, fflo, wth, wtl,
                                                      b2_l, x, x,
                                                      nullptr, nullptr, nullptr, nullptr,
                                                      MLPV, DIMV);
    }
}